// round 10
// baseline (speedup 1.0000x reference)
#include <cuda_runtime.h>

#define NN 50000
#define EE 800000
#define DD 128
#define NHH 8

// ---------------- device scratch (no allocations allowed) ----------------
__device__ __align__(16) float g_V[NN * DD];     // H @ Wv^T
__device__ __align__(16) float g_agg[NN * DD];   // aggregated messages
__device__ __align__(16) float g_Adst[NN * NHH]; // H @ (W4 W1)^T
__device__ __align__(16) float g_Asrc[NN * NHH]; // H @ (W4 W2)^T
__device__ __align__(16) float g_Wa[16 * DD];    // rows 0-7: W4@W1, rows 8-15: W4@W2
__device__ float g_c[NHH];                       // W3 . W4[h]
__device__ int   g_deg[NN];
__device__ int   g_offs[NN + 1];
__device__ int   g_cursor[NN];
__device__ int   g_srcs[EE];
__device__ float g_Pe[EE];
__device__ float g_De[EE];
__device__ __align__(16) float g_exp[EE * NHH];

// ---------------- prep: blocks 0-7 compute Wa/c, blocks 8+ zero counters ------
__global__ void k_prep(const float* __restrict__ W1, const float* __restrict__ W2,
                       const float* __restrict__ W3, const float* __restrict__ W4,
                       int n) {
    if (blockIdx.x < 8) {
        int t = blockIdx.x * 256 + threadIdx.x;   // 2048 threads
        if (t < 16 * DD) {
            int h16 = t >> 7;
            int d = t & 127;
            const float* Wsel = (h16 < 8) ? W1 : W2;
            int h = h16 & 7;
            float s = 0.f;
            for (int k = 0; k < DD; k++)
                s = fmaf(W4[h * DD + k], Wsel[k * DD + d], s);
            g_Wa[t] = s;
        }
        if (t < NHH) {
            float s = 0.f;
            for (int j = 0; j < DD; j++)
                s = fmaf(W3[j], W4[t * DD + j], s);
            g_c[t] = s;
        }
    } else {
        int i = (blockIdx.x - 8) * 256 + threadIdx.x;
        if (i < n) { g_deg[i] = 0; g_cursor[i] = 0; }
    }
}

// edge_index is int32 (JAX x64 disabled; jnp.int64 silently downcasts).
__global__ void k_hist(const int* __restrict__ ei, int e, int n) {
    int i = blockIdx.x * blockDim.x + threadIdx.x;
    if (i < e) {
        int dst = ei[e + i];
        dst = min(max(dst, 0), n - 1);   // defensive clamp: never trap
        atomicAdd(&g_deg[dst], 1);
    }
}

// single-block smem-tiled coarsened exclusive scan: g_deg -> g_offs
#define STILE 8192
__global__ void __launch_bounds__(1024) k_scan(int n) {
    __shared__ __align__(16) int sd[STILE];
    __shared__ int wsum[32];
    __shared__ int s_carry;
    int tid = threadIdx.x, lane = tid & 31, wid = tid >> 5;
    if (tid == 0) s_carry = 0;
    __syncthreads();

    for (int base = 0; base < n; base += STILE) {
        // coalesced load (zero-pad tail)
        #pragma unroll
        for (int k = 0; k < 8; k++) {
            int i = base + tid + k * 1024;
            sd[tid + k * 1024] = (i < n) ? g_deg[i] : 0;
        }
        __syncthreads();

        // each thread scans its 8 contiguous elements
        int4 v0 = *(const int4*)&sd[tid * 8];
        int4 v1 = *(const int4*)&sd[tid * 8 + 4];
        int loc[8] = {v0.x, v0.y, v0.z, v0.w, v1.x, v1.y, v1.z, v1.w};
        int s = 0;
        #pragma unroll
        for (int k = 0; k < 8; k++) s += loc[k];

        // warp inclusive scan of per-thread sums
        int x = s;
        #pragma unroll
        for (int o = 1; o < 32; o <<= 1) {
            int y = __shfl_up_sync(0xffffffffu, x, o);
            if (lane >= o) x += y;
        }
        if (lane == 31) wsum[wid] = x;
        __syncthreads();
        if (wid == 0) {
            int w = wsum[lane];
            #pragma unroll
            for (int o = 1; o < 32; o <<= 1) {
                int y = __shfl_up_sync(0xffffffffu, w, o);
                if (lane >= o) w += y;
            }
            wsum[lane] = w;
        }
        __syncthreads();

        int run = x - s + (wid ? wsum[wid - 1] : 0) + s_carry;  // exclusive
        int4 o0, o1;
        o0.x = run; run += loc[0];
        o0.y = run; run += loc[1];
        o0.z = run; run += loc[2];
        o0.w = run; run += loc[3];
        o1.x = run; run += loc[4];
        o1.y = run; run += loc[5];
        o1.z = run; run += loc[6];
        o1.w = run; run += loc[7];
        *(int4*)&sd[tid * 8]     = o0;
        *(int4*)&sd[tid * 8 + 4] = o1;
        __syncthreads();                 // all s_carry reads done
        if (tid == 1023) s_carry = run;  // tile total (incl carry)

        // coalesced store
        #pragma unroll
        for (int k = 0; k < 8; k++) {
            int i = base + tid + k * 1024;
            if (i < n) g_offs[i] = sd[tid + k * 1024];
        }
        __syncthreads();                 // s_carry visible, sd reusable
    }
    if (tid == 0) g_offs[n] = s_carry;
}

__global__ void k_scatter(const int* __restrict__ ei,
                          const float* __restrict__ P, const float* __restrict__ DT,
                          int e, int n) {
    int i = blockIdx.x * blockDim.x + threadIdx.x;
    if (i < e) {
        int src = ei[i];
        int dst = ei[e + i];
        src = min(max(src, 0), n - 1);
        dst = min(max(dst, 0), n - 1);
        int p = atomicAdd(&g_cursor[dst], 1);
        int j = g_offs[dst] + p;
        if (j >= 0 && j < e) {
            g_srcs[j] = src;
            g_Pe[j] = P[i];
            g_De[j] = DT[i];
        }
    }
}

// ---------------- K-chunked 128x128 GEMM machinery (static smem <=48KB) ----------
// Chunk tile: 128 rows x 32 k-cols, smem pitch 36 floats (144B, 16B-aligned rows).
#define CPITCH 36

__device__ __forceinline__ void load_chunk(float* S, const float* __restrict__ G,
                                           int row0, int nrows, int kc) {
    int tid = threadIdx.x;
    #pragma unroll
    for (int i = 0; i < 4; i++) {
        int f = tid + i * 256;            // 1024 float4s per chunk
        int row = f >> 3, q = f & 7;
        float4 v = make_float4(0.f, 0.f, 0.f, 0.f);
        if (row0 + row < nrows)
            v = *(const float4*)(G + (size_t)(row0 + row) * DD + kc * 32 + q * 4);
        *(float4*)(S + row * CPITCH + q * 4) = v;
    }
}

__device__ __forceinline__ void gemm_chunk(const float* Hs, const float* Ws,
                                           float acc[8][8], int tx, int ty) {
    #pragma unroll
    for (int kq = 0; kq < 8; kq++) {
        float4 a[8], b[8];
        #pragma unroll
        for (int i = 0; i < 8; i++)
            a[i] = *(const float4*)(Hs + (ty + 16 * i) * CPITCH + kq * 4);
        #pragma unroll
        for (int j = 0; j < 8; j++)
            b[j] = *(const float4*)(Ws + (tx + 16 * j) * CPITCH + kq * 4);
        #pragma unroll
        for (int i = 0; i < 8; i++)
            #pragma unroll
            for (int j = 0; j < 8; j++) {
                acc[i][j] = fmaf(a[i].x, b[j].x, acc[i][j]);
                acc[i][j] = fmaf(a[i].y, b[j].y, acc[i][j]);
                acc[i][j] = fmaf(a[i].z, b[j].z, acc[i][j]);
                acc[i][j] = fmaf(a[i].w, b[j].w, acc[i][j]);
            }
    }
}

// V = H@Wv^T ; Adst/Asrc = H @ Wa^T (folded chunk-wise)
__global__ void __launch_bounds__(256) k_nodeproj(const float* __restrict__ H,
                                                  const float* __restrict__ Wv, int n) {
    __shared__ float Hs[128 * CPITCH];
    __shared__ float Ws[128 * CPITCH];
    __shared__ float Was[16 * 32];
    int m0 = blockIdx.x * 128;
    int tid = threadIdx.x, tx = tid & 15, ty = tid >> 4;

    float acc[8][8];
    #pragma unroll
    for (int i = 0; i < 8; i++)
        #pragma unroll
        for (int j = 0; j < 8; j++) acc[i][j] = 0.f;
    float acc2[8];
    #pragma unroll
    for (int h = 0; h < 8; h++) acc2[h] = 0.f;
    int r = tid >> 1, half = tid & 1;

    for (int kc = 0; kc < 4; kc++) {
        load_chunk(Hs, H, m0, n, kc);
        load_chunk(Ws, Wv, 0, 128, kc);
        #pragma unroll
        for (int i = 0; i < 2; i++) {
            int f = tid + i * 256;    // 512 elements
            int wr = f >> 5, k = f & 31;
            Was[wr * 32 + k] = g_Wa[wr * DD + kc * 32 + k];
        }
        __syncthreads();
        gemm_chunk(Hs, Ws, acc, tx, ty);
        // attention projection: each (r, half) pair dots H row r with 8 Wa rows
        #pragma unroll
        for (int k = 0; k < 32; k++) {
            float hv = Hs[r * CPITCH + k];
            #pragma unroll
            for (int h = 0; h < 8; h++)
                acc2[h] = fmaf(hv, Was[(half * 8 + h) * 32 + k], acc2[h]);
        }
        __syncthreads();
    }
    #pragma unroll
    for (int i = 0; i < 8; i++) {
        int grow = m0 + ty + 16 * i;
        if (grow < n)
            #pragma unroll
            for (int j = 0; j < 8; j++)
                g_V[(size_t)grow * DD + tx + 16 * j] = acc[i][j];
    }
    int grow = m0 + r;
    if (grow < n) {
        float* dp = half ? (g_Asrc + (size_t)grow * 8) : (g_Adst + (size_t)grow * 8);
        #pragma unroll
        for (int h = 0; h < 8; h++) dp[h] = acc2[h];
    }
}

// ---------------- per-dst-node attention + aggregation (one warp per node) --------
// NOTE: softmax shift is algebraically free: exp(l)/sum(exp(l)) == exp(l-mx)/sum(exp(l-mx)).
// Logits here are O(10) << 88, so unshifted fp32 exp cannot overflow. One pass fewer.
__global__ void __launch_bounds__(256) k_attn(int n) {
    int gw = (int)((blockIdx.x * blockDim.x + threadIdx.x) >> 5);
    int lane = threadIdx.x & 31;
    if (gw >= n) return;
    int beg = g_offs[gw], end = g_offs[gw + 1];

    float adst[8], cv[8];
    #pragma unroll
    for (int h = 0; h < 8; h++) { adst[h] = g_Adst[(size_t)gw * 8 + h]; cv[h] = g_c[h]; }

    // pass 1: exp(logit) + per-head sum, cache exp values
    float sm8[8];
    #pragma unroll
    for (int h = 0; h < 8; h++) sm8[h] = 0.f;
    for (int j = beg + lane; j < end; j += 32) {
        int s = g_srcs[j];
        float p = g_Pe[j], dt = g_De[j];
        const float4* as4 = (const float4*)(g_Asrc + (size_t)s * 8);
        float4 a0 = as4[0], a1 = as4[1];
        float asv[8] = {a0.x, a0.y, a0.z, a0.w, a1.x, a1.y, a1.z, a1.w};
        float ex[8];
        #pragma unroll
        for (int h = 0; h < 8; h++) {
            float l = adst[h] + asv[h] + p * cv[h] + dt;
            l = (l >= 0.f) ? l : 0.2f * l;
            ex[h] = __expf(l);
            sm8[h] += ex[h];
        }
        *(float4*)(g_exp + (size_t)j * 8)     = make_float4(ex[0], ex[1], ex[2], ex[3]);
        *(float4*)(g_exp + (size_t)j * 8 + 4) = make_float4(ex[4], ex[5], ex[6], ex[7]);
    }
    #pragma unroll
    for (int h = 0; h < 8; h++)
        #pragma unroll
        for (int o = 16; o; o >>= 1)
            sm8[h] += __shfl_xor_sync(0xffffffffu, sm8[h], o);

    // pass 2: weighted aggregation; lane covers dims [lane*4, lane*4+4), head = lane>>2
    int h = lane >> 2;
    float dsel = (h & 4) ? ((h & 2) ? ((h & 1) ? sm8[7] : sm8[6]) : ((h & 1) ? sm8[5] : sm8[4]))
                         : ((h & 2) ? ((h & 1) ? sm8[3] : sm8[2]) : ((h & 1) ? sm8[1] : sm8[0]));
    float ri = __fdividef(1.0f, dsel + 1e-12f);

    float4 acc = make_float4(0.f, 0.f, 0.f, 0.f);
    const float4* Vv = (const float4*)g_V;
    #pragma unroll 2
    for (int j = beg; j < end; j++) {
        float a = g_exp[(size_t)j * 8 + h] * ri;
        int s = g_srcs[j];
        float4 v = Vv[(size_t)s * 32 + lane];
        acc.x = fmaf(a, v.x, acc.x);
        acc.y = fmaf(a, v.y, acc.y);
        acc.z = fmaf(a, v.z, acc.z);
        acc.w = fmaf(a, v.w, acc.w);
    }
    *(float4*)(g_agg + (size_t)gw * DD + lane * 4) = acc;
}

// --------- out = LN([agg|H] @ [Wout|res_w]^T + (Wout_b+res_b)), K=256 fused -------
__global__ void __launch_bounds__(256) k_out(const float* __restrict__ H,
                                             const float* __restrict__ Wout,
                                             const float* __restrict__ Woutb,
                                             const float* __restrict__ resw,
                                             const float* __restrict__ resb,
                                             const float* __restrict__ lng,
                                             const float* __restrict__ lnb,
                                             float* __restrict__ out, int n) {
    __shared__ float As[128 * CPITCH];
    __shared__ float Ws[128 * CPITCH];
    int m0 = blockIdx.x * 128;
    int tid = threadIdx.x, tx = tid & 15, ty = tid >> 4;

    float acc[8][8];
    #pragma unroll
    for (int i = 0; i < 8; i++)
        #pragma unroll
        for (int j = 0; j < 8; j++) acc[i][j] = 0.f;

    for (int kc = 0; kc < 8; kc++) {
        if (kc < 4) {
            load_chunk(As, g_agg, m0, n, kc);
            load_chunk(Ws, Wout, 0, 128, kc);
        } else {
            load_chunk(As, H, m0, n, kc - 4);
            load_chunk(Ws, resw, 0, 128, kc - 4);
        }
        __syncthreads();
        gemm_chunk(As, Ws, acc, tx, ty);
        __syncthreads();
    }

    // per-column constants for this thread's 8 output columns
    float wb[8], gv[8], bv[8];
    #pragma unroll
    for (int j = 0; j < 8; j++) {
        int col = tx + 16 * j;
        wb[j] = Woutb[col] + resb[col];
        gv[j] = lng[col];
        bv[j] = lnb[col];
    }

    // epilogue: bias + LayerNorm per row; row (ty+16i) lives in the 16 threads
    // sharing ty (one half-warp) -> xor shuffles 1/2/4/8 reduce within them.
    #pragma unroll
    for (int i = 0; i < 8; i++) {
        int grow = m0 + ty + 16 * i;
        float v[8];
        float s = 0.f, q = 0.f;
        #pragma unroll
        for (int j = 0; j < 8; j++) {
            float t = acc[i][j] + wb[j];
            v[j] = t;
            s += t;
            q = fmaf(t, t, q);
        }
        #pragma unroll
        for (int o = 8; o; o >>= 1) {
            s += __shfl_xor_sync(0xffffffffu, s, o);
            q += __shfl_xor_sync(0xffffffffu, q, o);
        }
        float mu  = s * (1.0f / 128.0f);
        float var = q * (1.0f / 128.0f) - mu * mu;
        float inv = rsqrtf(var + 1e-5f);
        if (grow < n) {
            #pragma unroll
            for (int j = 0; j < 8; j++)
                out[(size_t)grow * DD + tx + 16 * j] = (v[j] - mu) * inv * gv[j] + bv[j];
        }
    }
}

// ---------------- launcher ----------------
extern "C" void kernel_launch(void* const* d_in, const int* in_sizes, int n_in,
                              void* d_out, int out_size) {
    const float* H     = (const float*)d_in[0];
    const int*   EI    = (const int*)d_in[1];     // int32! (JAX x64 disabled)
    const float* P     = (const float*)d_in[2];
    const float* DT    = (const float*)d_in[3];
    const float* W1    = (const float*)d_in[4];
    const float* W2    = (const float*)d_in[5];
    const float* W3    = (const float*)d_in[6];
    const float* W4    = (const float*)d_in[7];
    const float* Wv    = (const float*)d_in[8];
    const float* Woutw = (const float*)d_in[9];
    const float* Woutb = (const float*)d_in[10];
    const float* resw  = (const float*)d_in[11];
    const float* resb  = (const float*)d_in[12];
    const float* lng   = (const float*)d_in[13];
    const float* lnb   = (const float*)d_in[14];
    float* out = (float*)d_out;

    int n = in_sizes[0] / DD;   // 50000
    int e = in_sizes[2];        // 800000

    k_prep<<<8 + (n + 255) / 256, 256>>>(W1, W2, W3, W4, n);
    k_hist<<<(e + 255) / 256, 256>>>(EI, e, n);
    k_scan<<<1, 1024>>>(n);
    k_scatter<<<(e + 255) / 256, 256>>>(EI, P, DT, e, n);
    k_nodeproj<<<(n + 127) / 128, 256>>>(H, Wv, n);
    k_attn<<<(n + 7) / 8, 256>>>(n);
    k_out<<<(n + 127) / 128, 256>>>(H, Woutw, Woutb, resw, resb, lng, lnb, out, n);
}

// round 12
// speedup vs baseline: 1.9805x; 1.9805x over previous
#include <cuda_runtime.h>
#include <cuda_bf16.h>
#include <cstdint>

#define NN 50000
#define EE 800000
#define DD 128
#define NHH 8

// ---------------- device scratch (no allocations allowed) ----------------
__device__ __align__(16) float g_V[NN * DD];     // H @ Wv^T
__device__ __align__(16) float g_agg[NN * DD];   // aggregated messages
__device__ __align__(16) float g_Adst[NN * NHH]; // H @ (W4 W1)^T
__device__ __align__(16) float g_Asrc[NN * NHH]; // H @ (W4 W2)^T
__device__ __align__(16) float g_Wa[16 * DD];    // rows 0-7: W4@W1, rows 8-15: W4@W2
__device__ float g_c[NHH];                       // W3 . W4[h]
__device__ int   g_deg[NN];
__device__ int   g_offs[NN + 1];
__device__ int   g_cursor[NN];
__device__ int   g_srcs[EE];
__device__ float g_Pe[EE];
__device__ float g_De[EE];
__device__ __align__(16) float g_exp[EE * NHH];

// ---------------- mma.sync bf16 split-precision GEMM machinery ----------------
// smem tiles: 128 rows x 64 bf16, pitch 72 bf16 (144B) -> fragment loads conflict-free
#define TPITCHB 144                    // bytes per tile row
#define T_AHI 0
#define T_ALO 18432
#define T_BHI 36864
#define T_BLO 55296
#define SM_GEMM 73728                  // 4 tiles; also >= 128*132*4 stage for k_out

__device__ __forceinline__ void mma16816(float* c, const uint32_t* a, const uint32_t* b) {
    asm volatile(
        "mma.sync.aligned.m16n8k16.row.col.f32.bf16.bf16.f32 "
        "{%0,%1,%2,%3}, {%4,%5,%6,%7}, {%8,%9}, {%0,%1,%2,%3};\n"
        : "+f"(c[0]), "+f"(c[1]), "+f"(c[2]), "+f"(c[3])
        : "r"(a[0]), "r"(a[1]), "r"(a[2]), "r"(a[3]), "r"(b[0]), "r"(b[1]));
}

// load 128x64 fp32 tile -> bf16 hi/lo into padded smem (256 threads)
__device__ __forceinline__ void ld_split(char* sm, int oh, int ol,
                                         const float* __restrict__ G,
                                         int row0, int nrows, int kcol0) {
    int t = threadIdx.x;
    #pragma unroll
    for (int i = 0; i < 8; i++) {
        int f = t + i * 256;           // 2048 float4s
        int row = f >> 4, kq = f & 15;
        float4 v = make_float4(0.f, 0.f, 0.f, 0.f);
        if (row0 + row < nrows)
            v = *(const float4*)(G + (size_t)(row0 + row) * DD + kcol0 + kq * 4);
        float xs[4] = {v.x, v.y, v.z, v.w};
        uint16_t hb[4], lb[4];
        #pragma unroll
        for (int q = 0; q < 4; q++) {
            __nv_bfloat16 h = __float2bfloat16(xs[q]);
            __nv_bfloat16 l = __float2bfloat16(xs[q] - __bfloat162float(h));
            hb[q] = __nv_bfloat16_raw(h).x;
            lb[q] = __nv_bfloat16_raw(l).x;
        }
        char* ph = sm + oh + row * TPITCHB + kq * 8;
        char* pl = sm + ol + row * TPITCHB + kq * 8;
        *(uint32_t*)ph       = (uint32_t)hb[1] << 16 | hb[0];
        *(uint32_t*)(ph + 4) = (uint32_t)hb[3] << 16 | hb[2];
        *(uint32_t*)pl       = (uint32_t)lb[1] << 16 | lb[0];
        *(uint32_t*)(pl + 4) = (uint32_t)lb[3] << 16 | lb[2];
    }
}

// one K=64 chunk of split MMAs; acc[2][8][4] per warp (warp tile 32x64)
__device__ __forceinline__ void mma_chunk(const char* sm, float acc[2][8][4],
                                          int warp_m, int warp_n, int lane) {
    int lr = lane >> 2, lc = lane & 3;
    #pragma unroll
    for (int ks = 0; ks < 4; ks++) {
        uint32_t ah[2][4], al[2][4], bh[8][2], bl[8][2];
        int kb = (ks * 16 + lc * 2) * 2;     // byte offset of k pair
        #pragma unroll
        for (int mt = 0; mt < 2; mt++) {
            int r = warp_m * 32 + mt * 16 + lr;
            const char* p = sm + T_AHI + r * TPITCHB + kb;
            ah[mt][0] = *(const uint32_t*)p;
            ah[mt][1] = *(const uint32_t*)(p + 8 * TPITCHB);
            ah[mt][2] = *(const uint32_t*)(p + 16);
            ah[mt][3] = *(const uint32_t*)(p + 8 * TPITCHB + 16);
            const char* q = sm + T_ALO + r * TPITCHB + kb;
            al[mt][0] = *(const uint32_t*)q;
            al[mt][1] = *(const uint32_t*)(q + 8 * TPITCHB);
            al[mt][2] = *(const uint32_t*)(q + 16);
            al[mt][3] = *(const uint32_t*)(q + 8 * TPITCHB + 16);
        }
        #pragma unroll
        for (int nt = 0; nt < 8; nt++) {
            int r = warp_n * 64 + nt * 8 + lr;
            const char* p = sm + T_BHI + r * TPITCHB + kb;
            bh[nt][0] = *(const uint32_t*)p;
            bh[nt][1] = *(const uint32_t*)(p + 16);
            const char* q = sm + T_BLO + r * TPITCHB + kb;
            bl[nt][0] = *(const uint32_t*)q;
            bl[nt][1] = *(const uint32_t*)(q + 16);
        }
        #pragma unroll
        for (int mt = 0; mt < 2; mt++)
            #pragma unroll
            for (int nt = 0; nt < 8; nt++) {
                mma16816(acc[mt][nt], ah[mt], bh[nt]);
                mma16816(acc[mt][nt], ah[mt], bl[nt]);
                mma16816(acc[mt][nt], al[mt], bh[nt]);
            }
    }
}

// ---------------- V = H @ Wv^T (tensor pipe) ----------------
__global__ void __launch_bounds__(256, 1) k_gemm_v(const float* __restrict__ H,
                                                   const float* __restrict__ Wv, int n) {
    extern __shared__ __align__(16) char sm[];
    int tid = threadIdx.x, wid = tid >> 5, lane = tid & 31;
    int warp_m = wid >> 1, warp_n = wid & 1;
    int m0 = blockIdx.x * 128;

    float acc[2][8][4];
    #pragma unroll
    for (int mt = 0; mt < 2; mt++)
        #pragma unroll
        for (int nt = 0; nt < 8; nt++)
            #pragma unroll
            for (int q = 0; q < 4; q++) acc[mt][nt][q] = 0.f;

    for (int c = 0; c < 2; c++) {
        ld_split(sm, T_AHI, T_ALO, H, m0, n, c * 64);
        ld_split(sm, T_BHI, T_BLO, Wv, 0, 128, c * 64);
        __syncthreads();
        mma_chunk(sm, acc, warp_m, warp_n, lane);
        __syncthreads();
    }

    int lr = lane >> 2, lc = lane & 3;
    #pragma unroll
    for (int mt = 0; mt < 2; mt++) {
        int r0 = m0 + warp_m * 32 + mt * 16 + lr;
        #pragma unroll
        for (int nt = 0; nt < 8; nt++) {
            int cc = warp_n * 64 + nt * 8 + lc * 2;
            if (r0 < n)
                *(float2*)(g_V + (size_t)r0 * DD + cc) =
                    make_float2(acc[mt][nt][0], acc[mt][nt][1]);
            if (r0 + 8 < n)
                *(float2*)(g_V + (size_t)(r0 + 8) * DD + cc) =
                    make_float2(acc[mt][nt][2], acc[mt][nt][3]);
        }
    }
}

// --------- out = LN([agg|H] @ [Wout|resw]^T + bias), K=256, tensor pipe ----------
__global__ void __launch_bounds__(256, 1) k_gemm_out(const float* __restrict__ H,
                                                     const float* __restrict__ Wout,
                                                     const float* __restrict__ Woutb,
                                                     const float* __restrict__ resw,
                                                     const float* __restrict__ resb,
                                                     const float* __restrict__ lng,
                                                     const float* __restrict__ lnb,
                                                     float* __restrict__ out, int n) {
    extern __shared__ __align__(16) char sm[];
    __shared__ __align__(16) float s_wb[128], s_g[128], s_b[128];
    int tid = threadIdx.x, wid = tid >> 5, lane = tid & 31;
    int warp_m = wid >> 1, warp_n = wid & 1;
    int m0 = blockIdx.x * 128;

    if (tid < 128) {
        s_wb[tid] = Woutb[tid] + resb[tid];
        s_g[tid] = lng[tid];
        s_b[tid] = lnb[tid];
    }

    float acc[2][8][4];
    #pragma unroll
    for (int mt = 0; mt < 2; mt++)
        #pragma unroll
        for (int nt = 0; nt < 8; nt++)
            #pragma unroll
            for (int q = 0; q < 4; q++) acc[mt][nt][q] = 0.f;

    for (int c = 0; c < 4; c++) {
        const float* As = (c < 2) ? g_agg : H;
        const float* Bs = (c < 2) ? Wout : resw;
        int kcol = (c & 1) * 64;
        ld_split(sm, T_AHI, T_ALO, As, m0, n, kcol);
        ld_split(sm, T_BHI, T_BLO, Bs, 0, 128, kcol);
        __syncthreads();
        mma_chunk(sm, acc, warp_m, warp_n, lane);
        __syncthreads();
    }

    // stage pre-LN rows in smem (reuse tile space), pitch 132 floats
    float* stg = (float*)sm;
    int lr = lane >> 2, lc = lane & 3;
    #pragma unroll
    for (int mt = 0; mt < 2; mt++) {
        int r0 = warp_m * 32 + mt * 16 + lr;
        #pragma unroll
        for (int nt = 0; nt < 8; nt++) {
            int cc = warp_n * 64 + nt * 8 + lc * 2;
            *(float2*)(stg + r0 * 132 + cc) = make_float2(acc[mt][nt][0], acc[mt][nt][1]);
            *(float2*)(stg + (r0 + 8) * 132 + cc) = make_float2(acc[mt][nt][2], acc[mt][nt][3]);
        }
    }
    __syncthreads();

    // LN: warp w handles rows [w*16, w*16+16)
    float4 wb4 = *(const float4*)(s_wb + lane * 4);
    float4 g4  = *(const float4*)(s_g + lane * 4);
    float4 b4  = *(const float4*)(s_b + lane * 4);
    for (int r = wid * 16; r < wid * 16 + 16; r++) {
        int grow = m0 + r;
        float4 v = *(const float4*)(stg + r * 132 + lane * 4);
        v.x += wb4.x; v.y += wb4.y; v.z += wb4.z; v.w += wb4.w;
        float s = v.x + v.y + v.z + v.w;
        float q = v.x * v.x + v.y * v.y + v.z * v.z + v.w * v.w;
        #pragma unroll
        for (int o = 16; o; o >>= 1) {
            s += __shfl_xor_sync(0xffffffffu, s, o);
            q += __shfl_xor_sync(0xffffffffu, q, o);
        }
        float mu  = s * (1.0f / 128.0f);
        float var = q * (1.0f / 128.0f) - mu * mu;
        float inv = rsqrtf(var + 1e-5f);
        if (grow < n) {
            float4 o4;
            o4.x = (v.x - mu) * inv * g4.x + b4.x;
            o4.y = (v.y - mu) * inv * g4.y + b4.y;
            o4.z = (v.z - mu) * inv * g4.z + b4.z;
            o4.w = (v.w - mu) * inv * g4.w + b4.w;
            *(float4*)(out + (size_t)grow * DD + lane * 4) = o4;
        }
    }
}

// ---------------- prep: blocks 0-7 compute Wa/c, blocks 8+ zero counters ------
__global__ void k_prep(const float* __restrict__ W1, const float* __restrict__ W2,
                       const float* __restrict__ W3, const float* __restrict__ W4,
                       int n) {
    if (blockIdx.x < 8) {
        int t = blockIdx.x * 256 + threadIdx.x;
        if (t < 16 * DD) {
            int h16 = t >> 7;
            int d = t & 127;
            const float* Wsel = (h16 < 8) ? W1 : W2;
            int h = h16 & 7;
            float s = 0.f;
            for (int k = 0; k < DD; k++)
                s = fmaf(W4[h * DD + k], Wsel[k * DD + d], s);
            g_Wa[t] = s;
        }
        if (t < NHH) {
            float s = 0.f;
            for (int j = 0; j < DD; j++)
                s = fmaf(W3[j], W4[t * DD + j], s);
            g_c[t] = s;
        }
    } else {
        int i = (blockIdx.x - 8) * 256 + threadIdx.x;
        if (i < n) { g_deg[i] = 0; g_cursor[i] = 0; }
    }
}

// edge_index is int32 (JAX x64 disabled; jnp.int64 silently downcasts).
__global__ void k_hist(const int* __restrict__ ei, int e, int n) {
    int i = blockIdx.x * blockDim.x + threadIdx.x;
    if (i < e) {
        int dst = ei[e + i];
        dst = min(max(dst, 0), n - 1);
        atomicAdd(&g_deg[dst], 1);
    }
}

// single-block smem-tiled coarsened exclusive scan: g_deg -> g_offs
#define STILE 8192
__global__ void __launch_bounds__(1024) k_scan(int n) {
    __shared__ __align__(16) int sd[STILE];
    __shared__ int wsum[32];
    __shared__ int s_carry;
    int tid = threadIdx.x, lane = tid & 31, wid = tid >> 5;
    if (tid == 0) s_carry = 0;
    __syncthreads();

    for (int base = 0; base < n; base += STILE) {
        #pragma unroll
        for (int k = 0; k < 8; k++) {
            int i = base + tid + k * 1024;
            sd[tid + k * 1024] = (i < n) ? g_deg[i] : 0;
        }
        __syncthreads();

        int4 v0 = *(const int4*)&sd[tid * 8];
        int4 v1 = *(const int4*)&sd[tid * 8 + 4];
        int loc[8] = {v0.x, v0.y, v0.z, v0.w, v1.x, v1.y, v1.z, v1.w};
        int s = 0;
        #pragma unroll
        for (int k = 0; k < 8; k++) s += loc[k];

        int x = s;
        #pragma unroll
        for (int o = 1; o < 32; o <<= 1) {
            int y = __shfl_up_sync(0xffffffffu, x, o);
            if (lane >= o) x += y;
        }
        if (lane == 31) wsum[wid] = x;
        __syncthreads();
        if (wid == 0) {
            int w = wsum[lane];
            #pragma unroll
            for (int o = 1; o < 32; o <<= 1) {
                int y = __shfl_up_sync(0xffffffffu, w, o);
                if (lane >= o) w += y;
            }
            wsum[lane] = w;
        }
        __syncthreads();

        int run = x - s + (wid ? wsum[wid - 1] : 0) + s_carry;
        int4 o0, o1;
        o0.x = run; run += loc[0];
        o0.y = run; run += loc[1];
        o0.z = run; run += loc[2];
        o0.w = run; run += loc[3];
        o1.x = run; run += loc[4];
        o1.y = run; run += loc[5];
        o1.z = run; run += loc[6];
        o1.w = run; run += loc[7];
        *(int4*)&sd[tid * 8]     = o0;
        *(int4*)&sd[tid * 8 + 4] = o1;
        __syncthreads();
        if (tid == 1023) s_carry = run;

        #pragma unroll
        for (int k = 0; k < 8; k++) {
            int i = base + tid + k * 1024;
            if (i < n) g_offs[i] = sd[tid + k * 1024];
        }
        __syncthreads();
    }
    if (tid == 0) g_offs[n] = s_carry;
}

__global__ void k_scatter(const int* __restrict__ ei,
                          const float* __restrict__ P, const float* __restrict__ DT,
                          int e, int n) {
    int i = blockIdx.x * blockDim.x + threadIdx.x;
    if (i < e) {
        int src = ei[i];
        int dst = ei[e + i];
        src = min(max(src, 0), n - 1);
        dst = min(max(dst, 0), n - 1);
        int p = atomicAdd(&g_cursor[dst], 1);
        int j = g_offs[dst] + p;
        if (j >= 0 && j < e) {
            g_srcs[j] = src;
            g_Pe[j] = P[i];
            g_De[j] = DT[i];
        }
    }
}

// ---------------- attention projection (fp32 SIMT, tiny N=16) ----------------
#define CPITCH 36
__global__ void __launch_bounds__(256) k_attnproj(const float* __restrict__ H, int n) {
    __shared__ float Hs[128 * CPITCH];
    __shared__ float Was[16 * 32];
    int m0 = blockIdx.x * 128;
    int tid = threadIdx.x;
    int r = tid >> 1, half = tid & 1;

    float acc2[8];
    #pragma unroll
    for (int h = 0; h < 8; h++) acc2[h] = 0.f;

    for (int kc = 0; kc < 4; kc++) {
        #pragma unroll
        for (int i = 0; i < 4; i++) {
            int f = tid + i * 256;
            int row = f >> 3, q = f & 7;
            float4 v = make_float4(0.f, 0.f, 0.f, 0.f);
            if (m0 + row < n)
                v = *(const float4*)(H + (size_t)(m0 + row) * DD + kc * 32 + q * 4);
            *(float4*)(Hs + row * CPITCH + q * 4) = v;
        }
        #pragma unroll
        for (int i = 0; i < 2; i++) {
            int f = tid + i * 256;
            int wr = f >> 5, k = f & 31;
            Was[wr * 32 + k] = g_Wa[wr * DD + kc * 32 + k];
        }
        __syncthreads();
        #pragma unroll
        for (int k = 0; k < 32; k++) {
            float hv = Hs[r * CPITCH + k];
            #pragma unroll
            for (int h = 0; h < 8; h++)
                acc2[h] = fmaf(hv, Was[(half * 8 + h) * 32 + k], acc2[h]);
        }
        __syncthreads();
    }
    int grow = m0 + r;
    if (grow < n) {
        float* dp = half ? (g_Asrc + (size_t)grow * 8) : (g_Adst + (size_t)grow * 8);
        #pragma unroll
        for (int h = 0; h < 8; h++) dp[h] = acc2[h];
    }
}

// ---------------- per-dst-node attention + aggregation (one warp per node) --------
__global__ void __launch_bounds__(256) k_attn(int n) {
    int gw = (int)((blockIdx.x * blockDim.x + threadIdx.x) >> 5);
    int lane = threadIdx.x & 31;
    if (gw >= n) return;
    int beg = g_offs[gw], end = g_offs[gw + 1];

    float adst[8], cv[8];
    #pragma unroll
    for (int h = 0; h < 8; h++) { adst[h] = g_Adst[(size_t)gw * 8 + h]; cv[h] = g_c[h]; }

    // pass 1: exp(logit) + per-head sum (softmax shift is algebraically free;
    // logits are O(10) << 88 so unshifted fp32 exp cannot overflow)
    float sm8[8];
    #pragma unroll
    for (int h = 0; h < 8; h++) sm8[h] = 0.f;
    for (int j = beg + lane; j < end; j += 32) {
        int s = g_srcs[j];
        float p = g_Pe[j], dt = g_De[j];
        const float4* as4 = (const float4*)(g_Asrc + (size_t)s * 8);
        float4 a0 = as4[0], a1 = as4[1];
        float asv[8] = {a0.x, a0.y, a0.z, a0.w, a1.x, a1.y, a1.z, a1.w};
        float ex[8];
        #pragma unroll
        for (int h = 0; h < 8; h++) {
            float l = adst[h] + asv[h] + p * cv[h] + dt;
            l = (l >= 0.f) ? l : 0.2f * l;
            ex[h] = __expf(l);
            sm8[h] += ex[h];
        }
        *(float4*)(g_exp + (size_t)j * 8)     = make_float4(ex[0], ex[1], ex[2], ex[3]);
        *(float4*)(g_exp + (size_t)j * 8 + 4) = make_float4(ex[4], ex[5], ex[6], ex[7]);
    }
    #pragma unroll
    for (int h = 0; h < 8; h++)
        #pragma unroll
        for (int o = 16; o; o >>= 1)
            sm8[h] += __shfl_xor_sync(0xffffffffu, sm8[h], o);

    // pass 2: weighted aggregation; lane covers dims [lane*4, lane*4+4), head = lane>>2
    int h = lane >> 2;
    float dsel = (h & 4) ? ((h & 2) ? ((h & 1) ? sm8[7] : sm8[6]) : ((h & 1) ? sm8[5] : sm8[4]))
                         : ((h & 2) ? ((h & 1) ? sm8[3] : sm8[2]) : ((h & 1) ? sm8[1] : sm8[0]));
    float ri = __fdividef(1.0f, dsel + 1e-12f);

    float4 acc = make_float4(0.f, 0.f, 0.f, 0.f);
    const float4* Vv = (const float4*)g_V;
    #pragma unroll 2
    for (int j = beg; j < end; j++) {
        float a = g_exp[(size_t)j * 8 + h] * ri;
        int s = g_srcs[j];
        float4 v = Vv[(size_t)s * 32 + lane];
        acc.x = fmaf(a, v.x, acc.x);
        acc.y = fmaf(a, v.y, acc.y);
        acc.z = fmaf(a, v.z, acc.z);
        acc.w = fmaf(a, v.w, acc.w);
    }
    *(float4*)(g_agg + (size_t)gw * DD + lane * 4) = acc;
}

// ---------------- launcher ----------------
extern "C" void kernel_launch(void* const* d_in, const int* in_sizes, int n_in,
                              void* d_out, int out_size) {
    const float* H     = (const float*)d_in[0];
    const int*   EI    = (const int*)d_in[1];     // int32! (JAX x64 disabled)
    const float* P     = (const float*)d_in[2];
    const float* DT    = (const float*)d_in[3];
    const float* W1    = (const float*)d_in[4];
    const float* W2    = (const float*)d_in[5];
    const float* W3    = (const float*)d_in[6];
    const float* W4    = (const float*)d_in[7];
    const float* Wv    = (const float*)d_in[8];
    const float* Woutw = (const float*)d_in[9];
    const float* Woutb = (const float*)d_in[10];
    const float* resw  = (const float*)d_in[11];
    const float* resb  = (const float*)d_in[12];
    const float* lng   = (const float*)d_in[13];
    const float* lnb   = (const float*)d_in[14];
    float* out = (float*)d_out;

    int n = in_sizes[0] / DD;   // 50000
    int e = in_sizes[2];        // 800000
    int gtiles = (n + 127) / 128;

    cudaFuncSetAttribute(k_gemm_v,   cudaFuncAttributeMaxDynamicSharedMemorySize, SM_GEMM);
    cudaFuncSetAttribute(k_gemm_out, cudaFuncAttributeMaxDynamicSharedMemorySize, SM_GEMM);

    k_prep<<<8 + (n + 255) / 256, 256>>>(W1, W2, W3, W4, n);
    k_hist<<<(e + 255) / 256, 256>>>(EI, e, n);
    k_scan<<<1, 1024>>>(n);
    k_scatter<<<(e + 255) / 256, 256>>>(EI, P, DT, e, n);
    k_attnproj<<<gtiles, 256>>>(H, n);
    k_gemm_v<<<gtiles, 256, SM_GEMM>>>(H, Wv, n);
    k_attn<<<(n + 7) / 8, 256>>>(n);
    k_gemm_out<<<gtiles, 256, SM_GEMM>>>(H, Woutw, Woutb, resw, resb, lng, lnb, out, n);
}

// round 13
// speedup vs baseline: 2.0875x; 1.0540x over previous
#include <cuda_runtime.h>
#include <cuda_bf16.h>
#include <cstdint>

#define NN 50000
#define EE 800000
#define DD 128
#define NHH 8

// ---------------- device scratch (no allocations allowed) ----------------
__device__ __align__(16) float g_V[NN * DD];     // H @ Wv^T
__device__ __align__(16) float g_agg[NN * DD];   // aggregated messages
__device__ __align__(16) float g_Adst[NN * NHH]; // H @ (W4 W1)^T
__device__ __align__(16) float g_Asrc[NN * NHH]; // H @ (W4 W2)^T
__device__ __align__(16) float g_Wa[16 * DD];    // rows 0-7: W4@W1, rows 8-15: W4@W2
__device__ float g_c[NHH];                       // W3 . W4[h]
__device__ int   g_deg[NN];
__device__ int   g_offs[NN + 1];
__device__ int   g_epos[EE];                     // per-edge slot within its dst bucket
__device__ int   g_srcs[EE];
__device__ float g_Pe[EE];
__device__ float g_De[EE];
__device__ __align__(16) float g_exp[EE * NHH];

// ---------------- mma.sync bf16 split-precision GEMM machinery ----------------
// smem tiles: 128 rows x 64 bf16, pitch 72 bf16 (144B) -> fragment loads conflict-free
#define TPITCHB 144                    // bytes per tile row
#define T_AHI 0
#define T_ALO 18432
#define T_BHI 36864
#define T_BLO 55296
#define SM_GEMM 73728                  // 4 tiles; also >= 128*132*4 stage for k_out

__device__ __forceinline__ void mma16816(float* c, const uint32_t* a, const uint32_t* b) {
    asm volatile(
        "mma.sync.aligned.m16n8k16.row.col.f32.bf16.bf16.f32 "
        "{%0,%1,%2,%3}, {%4,%5,%6,%7}, {%8,%9}, {%0,%1,%2,%3};\n"
        : "+f"(c[0]), "+f"(c[1]), "+f"(c[2]), "+f"(c[3])
        : "r"(a[0]), "r"(a[1]), "r"(a[2]), "r"(a[3]), "r"(b[0]), "r"(b[1]));
}

// load 128x64 fp32 tile -> bf16 hi/lo into padded smem (256 threads)
__device__ __forceinline__ void ld_split(char* sm, int oh, int ol,
                                         const float* __restrict__ G,
                                         int row0, int nrows, int kcol0) {
    int t = threadIdx.x;
    #pragma unroll
    for (int i = 0; i < 8; i++) {
        int f = t + i * 256;           // 2048 float4s
        int row = f >> 4, kq = f & 15;
        float4 v = make_float4(0.f, 0.f, 0.f, 0.f);
        if (row0 + row < nrows)
            v = *(const float4*)(G + (size_t)(row0 + row) * DD + kcol0 + kq * 4);
        float xs[4] = {v.x, v.y, v.z, v.w};
        uint16_t hb[4], lb[4];
        #pragma unroll
        for (int q = 0; q < 4; q++) {
            __nv_bfloat16 h = __float2bfloat16(xs[q]);
            __nv_bfloat16 l = __float2bfloat16(xs[q] - __bfloat162float(h));
            hb[q] = __nv_bfloat16_raw(h).x;
            lb[q] = __nv_bfloat16_raw(l).x;
        }
        char* ph = sm + oh + row * TPITCHB + kq * 8;
        char* pl = sm + ol + row * TPITCHB + kq * 8;
        *(uint32_t*)ph       = (uint32_t)hb[1] << 16 | hb[0];
        *(uint32_t*)(ph + 4) = (uint32_t)hb[3] << 16 | hb[2];
        *(uint32_t*)pl       = (uint32_t)lb[1] << 16 | lb[0];
        *(uint32_t*)(pl + 4) = (uint32_t)lb[3] << 16 | lb[2];
    }
}

// one K=64 chunk of split MMAs; acc[2][8][4] per warp (warp tile 32x64)
__device__ __forceinline__ void mma_chunk(const char* sm, float acc[2][8][4],
                                          int warp_m, int warp_n, int lane) {
    int lr = lane >> 2, lc = lane & 3;
    #pragma unroll
    for (int ks = 0; ks < 4; ks++) {
        uint32_t ah[2][4], al[2][4], bh[8][2], bl[8][2];
        int kb = (ks * 16 + lc * 2) * 2;     // byte offset of k pair
        #pragma unroll
        for (int mt = 0; mt < 2; mt++) {
            int r = warp_m * 32 + mt * 16 + lr;
            const char* p = sm + T_AHI + r * TPITCHB + kb;
            ah[mt][0] = *(const uint32_t*)p;
            ah[mt][1] = *(const uint32_t*)(p + 8 * TPITCHB);
            ah[mt][2] = *(const uint32_t*)(p + 16);
            ah[mt][3] = *(const uint32_t*)(p + 8 * TPITCHB + 16);
            const char* q = sm + T_ALO + r * TPITCHB + kb;
            al[mt][0] = *(const uint32_t*)q;
            al[mt][1] = *(const uint32_t*)(q + 8 * TPITCHB);
            al[mt][2] = *(const uint32_t*)(q + 16);
            al[mt][3] = *(const uint32_t*)(q + 8 * TPITCHB + 16);
        }
        #pragma unroll
        for (int nt = 0; nt < 8; nt++) {
            int r = warp_n * 64 + nt * 8 + lr;
            const char* p = sm + T_BHI + r * TPITCHB + kb;
            bh[nt][0] = *(const uint32_t*)p;
            bh[nt][1] = *(const uint32_t*)(p + 16);
            const char* q = sm + T_BLO + r * TPITCHB + kb;
            bl[nt][0] = *(const uint32_t*)q;
            bl[nt][1] = *(const uint32_t*)(q + 16);
        }
        #pragma unroll
        for (int mt = 0; mt < 2; mt++)
            #pragma unroll
            for (int nt = 0; nt < 8; nt++) {
                mma16816(acc[mt][nt], ah[mt], bh[nt]);
                mma16816(acc[mt][nt], ah[mt], bl[nt]);
                mma16816(acc[mt][nt], al[mt], bh[nt]);
            }
    }
}

// ---------------- V = H @ Wv^T (tensor) + attn projection (fp32, L2-warm) ------
#define WAPITCH 130
__global__ void __launch_bounds__(256, 1) k_gemm_v(const float* __restrict__ H,
                                                   const float* __restrict__ Wv, int n) {
    extern __shared__ __align__(16) char sm[];
    __shared__ float s_Wa[16 * WAPITCH];
    int tid = threadIdx.x, wid = tid >> 5, lane = tid & 31;
    int warp_m = wid >> 1, warp_n = wid & 1;
    int m0 = blockIdx.x * 128;

    // stage Wa (16x128) into padded smem
    #pragma unroll
    for (int i = 0; i < 8; i++) {
        int f = tid + i * 256;    // 2048 elements
        int wr = f >> 7, k = f & 127;
        s_Wa[wr * WAPITCH + k] = g_Wa[wr * DD + k];
    }

    float acc[2][8][4];
    #pragma unroll
    for (int mt = 0; mt < 2; mt++)
        #pragma unroll
        for (int nt = 0; nt < 8; nt++)
            #pragma unroll
            for (int q = 0; q < 4; q++) acc[mt][nt][q] = 0.f;

    for (int c = 0; c < 2; c++) {
        ld_split(sm, T_AHI, T_ALO, H, m0, n, c * 64);
        ld_split(sm, T_BHI, T_BLO, Wv, 0, 128, c * 64);
        __syncthreads();
        mma_chunk(sm, acc, warp_m, warp_n, lane);
        __syncthreads();
    }

    int lr = lane >> 2, lc = lane & 3;
    #pragma unroll
    for (int mt = 0; mt < 2; mt++) {
        int r0 = m0 + warp_m * 32 + mt * 16 + lr;
        #pragma unroll
        for (int nt = 0; nt < 8; nt++) {
            int cc = warp_n * 64 + nt * 8 + lc * 2;
            if (r0 < n)
                *(float2*)(g_V + (size_t)r0 * DD + cc) =
                    make_float2(acc[mt][nt][0], acc[mt][nt][1]);
            if (r0 + 8 < n)
                *(float2*)(g_V + (size_t)(r0 + 8) * DD + cc) =
                    make_float2(acc[mt][nt][2], acc[mt][nt][3]);
        }
    }

    // attention projection: thread pair (r, half) dots H row r (L2-warm) with 8 Wa rows
    int r = tid >> 1, half = tid & 1;
    int grow = m0 + r;
    if (grow < n) {
        float acc2[8];
        #pragma unroll
        for (int h = 0; h < 8; h++) acc2[h] = 0.f;
        const float4* hrow = (const float4*)(H + (size_t)grow * DD);
        const float* wbase = s_Wa + half * 8 * WAPITCH;
        #pragma unroll 4
        for (int kq = 0; kq < 32; kq++) {
            float4 hv = hrow[kq];
            #pragma unroll
            for (int h = 0; h < 8; h++) {
                const float* wr = wbase + h * WAPITCH + kq * 4;
                acc2[h] = fmaf(hv.x, wr[0], acc2[h]);
                acc2[h] = fmaf(hv.y, wr[1], acc2[h]);
                acc2[h] = fmaf(hv.z, wr[2], acc2[h]);
                acc2[h] = fmaf(hv.w, wr[3], acc2[h]);
            }
        }
        float* dp = half ? (g_Asrc + (size_t)grow * 8) : (g_Adst + (size_t)grow * 8);
        #pragma unroll
        for (int h = 0; h < 8; h++) dp[h] = acc2[h];
    }
}

// --------- out = LN([agg|H] @ [Wout|resw]^T + bias), K=256, tensor pipe ----------
__global__ void __launch_bounds__(256, 1) k_gemm_out(const float* __restrict__ H,
                                                     const float* __restrict__ Wout,
                                                     const float* __restrict__ Woutb,
                                                     const float* __restrict__ resw,
                                                     const float* __restrict__ resb,
                                                     const float* __restrict__ lng,
                                                     const float* __restrict__ lnb,
                                                     float* __restrict__ out, int n) {
    extern __shared__ __align__(16) char sm[];
    __shared__ __align__(16) float s_wb[128], s_g[128], s_b[128];
    int tid = threadIdx.x, wid = tid >> 5, lane = tid & 31;
    int warp_m = wid >> 1, warp_n = wid & 1;
    int m0 = blockIdx.x * 128;

    if (tid < 128) {
        s_wb[tid] = Woutb[tid] + resb[tid];
        s_g[tid] = lng[tid];
        s_b[tid] = lnb[tid];
    }

    float acc[2][8][4];
    #pragma unroll
    for (int mt = 0; mt < 2; mt++)
        #pragma unroll
        for (int nt = 0; nt < 8; nt++)
            #pragma unroll
            for (int q = 0; q < 4; q++) acc[mt][nt][q] = 0.f;

    for (int c = 0; c < 4; c++) {
        const float* As = (c < 2) ? g_agg : H;
        const float* Bs = (c < 2) ? Wout : resw;
        int kcol = (c & 1) * 64;
        ld_split(sm, T_AHI, T_ALO, As, m0, n, kcol);
        ld_split(sm, T_BHI, T_BLO, Bs, 0, 128, kcol);
        __syncthreads();
        mma_chunk(sm, acc, warp_m, warp_n, lane);
        __syncthreads();
    }

    // stage pre-LN rows in smem (reuse tile space), pitch 132 floats
    float* stg = (float*)sm;
    int lr = lane >> 2, lc = lane & 3;
    #pragma unroll
    for (int mt = 0; mt < 2; mt++) {
        int r0 = warp_m * 32 + mt * 16 + lr;
        #pragma unroll
        for (int nt = 0; nt < 8; nt++) {
            int cc = warp_n * 64 + nt * 8 + lc * 2;
            *(float2*)(stg + r0 * 132 + cc) = make_float2(acc[mt][nt][0], acc[mt][nt][1]);
            *(float2*)(stg + (r0 + 8) * 132 + cc) = make_float2(acc[mt][nt][2], acc[mt][nt][3]);
        }
    }
    __syncthreads();

    // LN: warp w handles rows [w*16, w*16+16)
    float4 wb4 = *(const float4*)(s_wb + lane * 4);
    float4 g4  = *(const float4*)(s_g + lane * 4);
    float4 b4  = *(const float4*)(s_b + lane * 4);
    for (int r = wid * 16; r < wid * 16 + 16; r++) {
        int grow = m0 + r;
        float4 v = *(const float4*)(stg + r * 132 + lane * 4);
        v.x += wb4.x; v.y += wb4.y; v.z += wb4.z; v.w += wb4.w;
        float s = v.x + v.y + v.z + v.w;
        float q = v.x * v.x + v.y * v.y + v.z * v.z + v.w * v.w;
        #pragma unroll
        for (int o = 16; o; o >>= 1) {
            s += __shfl_xor_sync(0xffffffffu, s, o);
            q += __shfl_xor_sync(0xffffffffu, q, o);
        }
        float mu  = s * (1.0f / 128.0f);
        float var = q * (1.0f / 128.0f) - mu * mu;
        float inv = rsqrtf(var + 1e-5f);
        if (grow < n) {
            float4 o4;
            o4.x = (v.x - mu) * inv * g4.x + b4.x;
            o4.y = (v.y - mu) * inv * g4.y + b4.y;
            o4.z = (v.z - mu) * inv * g4.z + b4.z;
            o4.w = (v.w - mu) * inv * g4.w + b4.w;
            *(float4*)(out + (size_t)grow * DD + lane * 4) = o4;
        }
    }
}

// ---------------- prep: blocks 0-7 compute Wa/c, blocks 8+ zero counters ------
__global__ void k_prep(const float* __restrict__ W1, const float* __restrict__ W2,
                       const float* __restrict__ W3, const float* __restrict__ W4,
                       int n) {
    if (blockIdx.x < 8) {
        int t = blockIdx.x * 256 + threadIdx.x;
        if (t < 16 * DD) {
            int h16 = t >> 7;
            int d = t & 127;
            const float* Wsel = (h16 < 8) ? W1 : W2;
            int h = h16 & 7;
            float s = 0.f;
            for (int k = 0; k < DD; k++)
                s = fmaf(W4[h * DD + k], Wsel[k * DD + d], s);
            g_Wa[t] = s;
        }
        if (t < NHH) {
            float s = 0.f;
            for (int j = 0; j < DD; j++)
                s = fmaf(W3[j], W4[t * DD + j], s);
            g_c[t] = s;
        }
    } else {
        int i = (blockIdx.x - 8) * 256 + threadIdx.x;
        if (i < n) g_deg[i] = 0;
    }
}

// edge_index is int32 (JAX x64 disabled; jnp.int64 silently downcasts).
// Record each edge's slot within its dst bucket -> scatter needs no atomics.
__global__ void k_hist(const int* __restrict__ ei, int e, int n) {
    int i = blockIdx.x * blockDim.x + threadIdx.x;
    if (i < e) {
        int dst = ei[e + i];
        dst = min(max(dst, 0), n - 1);
        g_epos[i] = atomicAdd(&g_deg[dst], 1);
    }
}

// single-block smem-tiled coarsened exclusive scan: g_deg -> g_offs
#define STILE 8192
__global__ void __launch_bounds__(1024) k_scan(int n) {
    __shared__ __align__(16) int sd[STILE];
    __shared__ int wsum[32];
    __shared__ int s_carry;
    int tid = threadIdx.x, lane = tid & 31, wid = tid >> 5;
    if (tid == 0) s_carry = 0;
    __syncthreads();

    for (int base = 0; base < n; base += STILE) {
        #pragma unroll
        for (int k = 0; k < 8; k++) {
            int i = base + tid + k * 1024;
            sd[tid + k * 1024] = (i < n) ? g_deg[i] : 0;
        }
        __syncthreads();

        int4 v0 = *(const int4*)&sd[tid * 8];
        int4 v1 = *(const int4*)&sd[tid * 8 + 4];
        int loc[8] = {v0.x, v0.y, v0.z, v0.w, v1.x, v1.y, v1.z, v1.w};
        int s = 0;
        #pragma unroll
        for (int k = 0; k < 8; k++) s += loc[k];

        int x = s;
        #pragma unroll
        for (int o = 1; o < 32; o <<= 1) {
            int y = __shfl_up_sync(0xffffffffu, x, o);
            if (lane >= o) x += y;
        }
        if (lane == 31) wsum[wid] = x;
        __syncthreads();
        if (wid == 0) {
            int w = wsum[lane];
            #pragma unroll
            for (int o = 1; o < 32; o <<= 1) {
                int y = __shfl_up_sync(0xffffffffu, w, o);
                if (lane >= o) w += y;
            }
            wsum[lane] = w;
        }
        __syncthreads();

        int run = x - s + (wid ? wsum[wid - 1] : 0) + s_carry;
        int4 o0, o1;
        o0.x = run; run += loc[0];
        o0.y = run; run += loc[1];
        o0.z = run; run += loc[2];
        o0.w = run; run += loc[3];
        o1.x = run; run += loc[4];
        o1.y = run; run += loc[5];
        o1.z = run; run += loc[6];
        o1.w = run; run += loc[7];
        *(int4*)&sd[tid * 8]     = o0;
        *(int4*)&sd[tid * 8 + 4] = o1;
        __syncthreads();
        if (tid == 1023) s_carry = run;

        #pragma unroll
        for (int k = 0; k < 8; k++) {
            int i = base + tid + k * 1024;
            if (i < n) g_offs[i] = sd[tid + k * 1024];
        }
        __syncthreads();
    }
    if (tid == 0) g_offs[n] = s_carry;
}

// atomic-free scatter: slot comes from g_epos recorded during hist
__global__ void k_scatter(const int* __restrict__ ei,
                          const float* __restrict__ P, const float* __restrict__ DT,
                          int e, int n) {
    int i = blockIdx.x * blockDim.x + threadIdx.x;
    if (i < e) {
        int src = ei[i];
        int dst = ei[e + i];
        src = min(max(src, 0), n - 1);
        dst = min(max(dst, 0), n - 1);
        int j = g_offs[dst] + g_epos[i];
        if (j >= 0 && j < e) {
            g_srcs[j] = src;
            g_Pe[j] = P[i];
            g_De[j] = DT[i];
        }
    }
}

// ---------------- per-dst-node attention + aggregation (one warp per node) --------
__global__ void __launch_bounds__(256) k_attn(int n) {
    int gw = (int)((blockIdx.x * blockDim.x + threadIdx.x) >> 5);
    int lane = threadIdx.x & 31;
    if (gw >= n) return;
    int beg = g_offs[gw], end = g_offs[gw + 1];

    float adst[8], cv[8];
    #pragma unroll
    for (int h = 0; h < 8; h++) { adst[h] = g_Adst[(size_t)gw * 8 + h]; cv[h] = g_c[h]; }

    // pass 1: exp(logit) + per-head sum (softmax shift is algebraically free;
    // logits are O(10) << 88 so unshifted fp32 exp cannot overflow)
    float sm8[8];
    #pragma unroll
    for (int h = 0; h < 8; h++) sm8[h] = 0.f;
    for (int j = beg + lane; j < end; j += 32) {
        int s = g_srcs[j];
        float p = g_Pe[j], dt = g_De[j];
        const float4* as4 = (const float4*)(g_Asrc + (size_t)s * 8);
        float4 a0 = as4[0], a1 = as4[1];
        float asv[8] = {a0.x, a0.y, a0.z, a0.w, a1.x, a1.y, a1.z, a1.w};
        float ex[8];
        #pragma unroll
        for (int h = 0; h < 8; h++) {
            float l = adst[h] + asv[h] + p * cv[h] + dt;
            l = (l >= 0.f) ? l : 0.2f * l;
            ex[h] = __expf(l);
            sm8[h] += ex[h];
        }
        *(float4*)(g_exp + (size_t)j * 8)     = make_float4(ex[0], ex[1], ex[2], ex[3]);
        *(float4*)(g_exp + (size_t)j * 8 + 4) = make_float4(ex[4], ex[5], ex[6], ex[7]);
    }
    #pragma unroll
    for (int h = 0; h < 8; h++)
        #pragma unroll
        for (int o = 16; o; o >>= 1)
            sm8[h] += __shfl_xor_sync(0xffffffffu, sm8[h], o);

    // pass 2: weighted aggregation; lane covers dims [lane*4, lane*4+4), head = lane>>2
    int h = lane >> 2;
    float dsel = (h & 4) ? ((h & 2) ? ((h & 1) ? sm8[7] : sm8[6]) : ((h & 1) ? sm8[5] : sm8[4]))
                         : ((h & 2) ? ((h & 1) ? sm8[3] : sm8[2]) : ((h & 1) ? sm8[1] : sm8[0]));
    float ri = __fdividef(1.0f, dsel + 1e-12f);

    float4 acc = make_float4(0.f, 0.f, 0.f, 0.f);
    const float4* Vv = (const float4*)g_V;
    #pragma unroll 4
    for (int j = beg; j < end; j++) {
        float a = g_exp[(size_t)j * 8 + h] * ri;
        int s = g_srcs[j];
        float4 v = Vv[(size_t)s * 32 + lane];
        acc.x = fmaf(a, v.x, acc.x);
        acc.y = fmaf(a, v.y, acc.y);
        acc.z = fmaf(a, v.z, acc.z);
        acc.w = fmaf(a, v.w, acc.w);
    }
    *(float4*)(g_agg + (size_t)gw * DD + lane * 4) = acc;
}

// ---------------- launcher ----------------
extern "C" void kernel_launch(void* const* d_in, const int* in_sizes, int n_in,
                              void* d_out, int out_size) {
    const float* H     = (const float*)d_in[0];
    const int*   EI    = (const int*)d_in[1];     // int32! (JAX x64 disabled)
    const float* P     = (const float*)d_in[2];
    const float* DT    = (const float*)d_in[3];
    const float* W1    = (const float*)d_in[4];
    const float* W2    = (const float*)d_in[5];
    const float* W3    = (const float*)d_in[6];
    const float* W4    = (const float*)d_in[7];
    const float* Wv    = (const float*)d_in[8];
    const float* Woutw = (const float*)d_in[9];
    const float* Woutb = (const float*)d_in[10];
    const float* resw  = (const float*)d_in[11];
    const float* resb  = (const float*)d_in[12];
    const float* lng   = (const float*)d_in[13];
    const float* lnb   = (const float*)d_in[14];
    float* out = (float*)d_out;

    int n = in_sizes[0] / DD;   // 50000
    int e = in_sizes[2];        // 800000
    int gtiles = (n + 127) / 128;

    cudaFuncSetAttribute(k_gemm_v,   cudaFuncAttributeMaxDynamicSharedMemorySize, SM_GEMM);
    cudaFuncSetAttribute(k_gemm_out, cudaFuncAttributeMaxDynamicSharedMemorySize, SM_GEMM);

    k_prep<<<8 + (n + 255) / 256, 256>>>(W1, W2, W3, W4, n);
    k_hist<<<(e + 255) / 256, 256>>>(EI, e, n);
    k_scan<<<1, 1024>>>(n);
    k_scatter<<<(e + 255) / 256, 256>>>(EI, P, DT, e, n);
    k_gemm_v<<<gtiles, 256, SM_GEMM>>>(H, Wv, n);
    k_attn<<<(n + 7) / 8, 256>>>(n);
    k_gemm_out<<<gtiles, 256, SM_GEMM>>>(H, Woutw, Woutb, resw, resb, lng, lnb, out, n);
}